// round 16
// baseline (speedup 1.0000x reference)
#include <cuda_runtime.h>
#include <cuda_bf16.h>

#define BATCH 4
#define SEQ   1024
#define DM    1024
#define HEADS 16
#define HD    64
#define BH    (BATCH*HEADS)
#define MTOK  (BATCH*SEQ)          // 4096
#define KP    (DM/2)               // 512 packed pairs per row
#define OFFIN ((unsigned)MTOK*KP)
#define WOFF  ((unsigned)DM*KP)

// ---------------- scratch (device globals; no allocs allowed) ----------------
__device__ unsigned g_inh[3u*MTOK*KP], g_inl[3u*MTOK*KP];   // packed inputs (q,k,v)
__device__ unsigned g_wh[4u*DM*KP],   g_wl[4u*DM*KP];       // packed weights (col-major)
__device__ unsigned g_Qh[MTOK*KP],    g_Ql[MTOK*KP];        // packed Q projection (pre-scaled by 1/8)
__device__ unsigned g_Kph[(size_t)BH*SEQ*32], g_Kpl[(size_t)BH*SEQ*32];  // K^T packed
__device__ unsigned g_Vph[(size_t)BH*HD*512], g_Vpl[(size_t)BH*HD*512];  // V packed
__device__ unsigned g_Oh[MTOK*KP],    g_Ol[MTOK*KP];        // packed attention out
__device__ unsigned g_Eh[SEQ*(HD/2)];                       // packed Er (hi only)

// ---------------- helpers ----------------
__device__ __forceinline__ void split2(float2 v, unsigned &h, unsigned &l) {
    __nv_bfloat162 bh = __float22bfloat162_rn(v);
    float2 back = __bfloat1622float2(bh);
    __nv_bfloat162 bl = __float22bfloat162_rn(make_float2(v.x - back.x, v.y - back.y));
    h = *(unsigned*)&bh;
    l = *(unsigned*)&bl;
}

__device__ __forceinline__ unsigned sptr(const void* p) {
    return (unsigned)__cvta_generic_to_shared(p);
}

__device__ __forceinline__ void cpa16(unsigned dst, const void* src) {
    asm volatile("cp.async.cg.shared.global [%0], [%1], 16;" :: "r"(dst), "l"(src) : "memory");
}

__device__ __forceinline__ void ldsm4(unsigned r[4], unsigned a) {
    asm volatile("ldmatrix.sync.aligned.m8n8.x4.shared.b16 {%0,%1,%2,%3}, [%4];"
        : "=r"(r[0]), "=r"(r[1]), "=r"(r[2]), "=r"(r[3]) : "r"(a));
}

__device__ __forceinline__ void mma_bf16(float c[4], const unsigned a[4], const unsigned b[2]) {
    asm volatile(
        "mma.sync.aligned.m16n8k16.row.col.f32.bf16.bf16.f32 "
        "{%0,%1,%2,%3},{%4,%5,%6,%7},{%8,%9},{%0,%1,%2,%3};\n"
        : "+f"(c[0]), "+f"(c[1]), "+f"(c[2]), "+f"(c[3])
        : "r"(a[0]), "r"(a[1]), "r"(a[2]), "r"(a[3]), "r"(b[0]), "r"(b[1]));
}

// one k16 slab (pair base pb), TN n8-tiles (TN even), 3-term split MMA, ldmatrix feeds.
template<int TN, int PA, int PB>
__device__ __forceinline__ void mma_k16_3(float (*acc)[4],
    const unsigned (*Ah)[PA], const unsigned (*Al)[PA],
    const unsigned (*Bh)[PB], const unsigned (*Bl)[PB],
    int arow, int pb, int lane)
{
    const int ar = arow + (lane & 15);
    const int ac = pb + ((lane >> 4) << 2);
    unsigned ah[4], al[4];
    ldsm4(ah, sptr(&Ah[ar][ac]));
    ldsm4(al, sptr(&Al[ar][ac]));
    const int br = (lane & 7) + ((lane & 16) >> 1);
    const int bc = pb + ((lane & 8) >> 1);
    #pragma unroll
    for (int t2 = 0; t2 < TN / 2; t2++) {
        unsigned bh[4], bl[4];
        ldsm4(bh, sptr(&Bh[t2 * 16 + br][bc]));
        ldsm4(bl, sptr(&Bl[t2 * 16 + br][bc]));
        mma_bf16(acc[2 * t2],     ah, &bh[0]);
        mma_bf16(acc[2 * t2],     al, &bh[0]);
        mma_bf16(acc[2 * t2],     ah, &bl[0]);
        mma_bf16(acc[2 * t2 + 1], ah, &bh[2]);
        mma_bf16(acc[2 * t2 + 1], al, &bh[2]);
        mma_bf16(acc[2 * t2 + 1], ah, &bl[2]);
    }
}

template<int TN, int PA, int PB>
__device__ __forceinline__ void mma_k16_1(float (*acc)[4],
    const unsigned (*Ah)[PA], const unsigned (*Bh)[PB],
    int arow, int pb, int lane)
{
    const int ar = arow + (lane & 15);
    const int ac = pb + ((lane >> 4) << 2);
    unsigned ah[4];
    ldsm4(ah, sptr(&Ah[ar][ac]));
    const int br = (lane & 7) + ((lane & 16) >> 1);
    const int bc = pb + ((lane & 8) >> 1);
    #pragma unroll
    for (int t2 = 0; t2 < TN / 2; t2++) {
        unsigned bh[4];
        ldsm4(bh, sptr(&Bh[t2 * 16 + br][bc]));
        mma_bf16(acc[2 * t2],     ah, &bh[0]);
        mma_bf16(acc[2 * t2 + 1], ah, &bh[2]);
    }
}

// ==================== pack kernels ====================
__global__ __launch_bounds__(256) void pack_rm3(const float* __restrict__ s0,
                                                const float* __restrict__ s1,
                                                const float* __restrict__ s2)
{
    const int z = blockIdx.y;
    const float* src = (z == 0) ? s0 : (z == 1) ? s1 : s2;
    unsigned* dh = g_inh + (unsigned)z * OFFIN;
    unsigned* dl = g_inl + (unsigned)z * OFFIN;
    const int i = blockIdx.x * 256 + threadIdx.x;
    const float4 a = ((const float4*)src)[2 * i], b = ((const float4*)src)[2 * i + 1];
    unsigned h0, l0, h1, l1, h2, l2, h3, l3;
    split2(make_float2(a.x, a.y), h0, l0);
    split2(make_float2(a.z, a.w), h1, l1);
    split2(make_float2(b.x, b.y), h2, l2);
    split2(make_float2(b.z, b.w), h3, l3);
    ((uint4*)dh)[i] = make_uint4(h0, h1, h2, h3);
    ((uint4*)dl)[i] = make_uint4(l0, l1, l2, l3);
}

__global__ __launch_bounds__(256) void pack_er(const float* __restrict__ Er, int n8)
{
    const int i = blockIdx.x * 256 + threadIdx.x;
    if (i < n8) {
        const float4 a = ((const float4*)Er)[2 * i], b = ((const float4*)Er)[2 * i + 1];
        unsigned h0, l0, h1, l1, h2, l2, h3, l3;
        split2(make_float2(a.x, a.y), h0, l0);
        split2(make_float2(a.z, a.w), h1, l1);
        split2(make_float2(b.x, b.y), h2, l2);
        split2(make_float2(b.z, b.w), h3, l3);
        ((uint4*)g_Eh)[i] = make_uint4(h0, h1, h2, h3);
    }
}

__global__ __launch_bounds__(256) void pack_cm4(const float* __restrict__ W0,
                                                const float* __restrict__ W1,
                                                const float* __restrict__ W2,
                                                const float* __restrict__ W3)
{
    __shared__ float s[64][68];   // pitch 68: float4 stores stay 16B-aligned
    const int z = blockIdx.z;
    const float* W = (z == 0) ? W0 : (z == 1) ? W1 : (z == 2) ? W2 : W3;
    unsigned* dh = g_wh + (unsigned)z * WOFF;
    unsigned* dl = g_wl + (unsigned)z * WOFF;
    const int tid = threadIdx.x;
    const int k0 = blockIdx.y * 64, c0 = blockIdx.x * 64;
    #pragma unroll
    for (int it = 0; it < 4; it++) {
        const int idx = tid + it * 256;
        const int kr = idx >> 4, cc = (idx & 15) * 4;
        *(float4*)&s[kr][cc] = *(const float4*)(W + (size_t)(k0 + kr) * DM + c0 + cc);
    }
    __syncthreads();
    const int c = tid >> 2, ch = tid & 3;
    unsigned h[8], l[8];
    #pragma unroll
    for (int p = 0; p < 8; p++) {
        const int kp = ch * 8 + p;
        split2(make_float2(s[2 * kp][c], s[2 * kp + 1][c]), h[p], l[p]);
    }
    unsigned* oh = dh + (size_t)(c0 + c) * KP + (k0 >> 1) + ch * 8;
    unsigned* ol = dl + (size_t)(c0 + c) * KP + (k0 >> 1) + ch * 8;
    *(uint4*)oh       = make_uint4(h[0], h[1], h[2], h[3]);
    *(uint4*)(oh + 4) = make_uint4(h[4], h[5], h[6], h[7]);
    *(uint4*)ol       = make_uint4(l[0], l[1], l[2], l[3]);
    *(uint4*)(ol + 4) = make_uint4(l[4], l[5], l[6], l[7]);
}

// ==================== packed GEMM: 4-stage cp.async ring, BK=16 ====================
struct GSmem { unsigned A[4][2][128][12]; unsigned B[4][2][128][12]; };   // 96 KB

__device__ __forceinline__ void mma16p(const unsigned (*Ah)[12], const unsigned (*Al)[12],
                                       const unsigned (*Bh)[12], const unsigned (*Bl)[12],
                                       float (*acc)[4][4], int warp_m, int warp_n, int lane) {
    const int arl = lane & 15, acl = (lane >> 4) << 2;
    const int brl = (lane & 7) + ((lane & 16) >> 1), bcl = (lane & 8) >> 1;
    unsigned ah[4][4], al[4][4], bh[2][4], bl[2][4];
    #pragma unroll
    for (int tm = 0; tm < 4; tm++) {
        ldsm4(ah[tm], sptr(&Ah[warp_m + tm * 16 + arl][acl]));
        ldsm4(al[tm], sptr(&Al[warp_m + tm * 16 + arl][acl]));
    }
    #pragma unroll
    for (int t2 = 0; t2 < 2; t2++) {
        ldsm4(bh[t2], sptr(&Bh[warp_n + t2 * 16 + brl][bcl]));
        ldsm4(bl[t2], sptr(&Bl[warp_n + t2 * 16 + brl][bcl]));
    }
    #pragma unroll
    for (int tm = 0; tm < 4; tm++)
        #pragma unroll
        for (int t2 = 0; t2 < 2; t2++) {
            mma_bf16(acc[tm][2 * t2],     ah[tm], &bh[t2][0]);
            mma_bf16(acc[tm][2 * t2],     al[tm], &bh[t2][0]);
            mma_bf16(acc[tm][2 * t2],     ah[tm], &bl[t2][0]);
            mma_bf16(acc[tm][2 * t2 + 1], ah[tm], &bh[t2][2]);
            mma_bf16(acc[tm][2 * t2 + 1], al[tm], &bh[t2][2]);
            mma_bf16(acc[tm][2 * t2 + 1], ah[tm], &bl[t2][2]);
        }
}

// mode: 0 = fp32 out (Cf), 1 = packed Q (scaled), 2 = packed K flash layout,
//       3 = packed V flash layout
__device__ __forceinline__ void gemm_body(
    const unsigned* Agh, const unsigned* Agl,
    const unsigned* Bgh, const unsigned* Bgl,
    float* Cf, unsigned* Ch, unsigned* Cl, float cscale, int mode,
    GSmem* sm, int m0, int n0)
{
    const int tid = threadIdx.x, lane = tid & 31, w = tid >> 5;
    const int warp_m = (w >> 2) * 64, warp_n = (w & 3) * 32;
    const int lrow = tid >> 1, loff = (tid & 1) << 2;
    const unsigned* Ash = Agh + (size_t)(m0 + lrow) * KP + loff;
    const unsigned* Asl = Agl + (size_t)(m0 + lrow) * KP + loff;
    const unsigned* Bsh = Bgh + (size_t)(n0 + lrow) * KP + loff;
    const unsigned* Bsl = Bgl + (size_t)(n0 + lrow) * KP + loff;

    auto load = [&](int s, int st) {
        const int kp0 = s << 3;
        cpa16(sptr(&sm->A[st][0][lrow][loff]), Ash + kp0);
        cpa16(sptr(&sm->A[st][1][lrow][loff]), Asl + kp0);
        cpa16(sptr(&sm->B[st][0][lrow][loff]), Bsh + kp0);
        cpa16(sptr(&sm->B[st][1][lrow][loff]), Bsl + kp0);
        asm volatile("cp.async.commit_group;" ::: "memory");
    };

    float acc[4][4][4] = {};
    load(0, 0); load(1, 1); load(2, 2);
    for (int s = 0; s < 64; s++) {
        const int st = s & 3;
        asm volatile("cp.async.wait_group 2;" ::: "memory");
        __syncthreads();
        if (s < 61) load(s + 3, (s + 3) & 3);
        else        asm volatile("cp.async.commit_group;" ::: "memory");
        mma16p(sm->A[st][0], sm->A[st][1], sm->B[st][0], sm->B[st][1],
               acc, warp_m, warp_n, lane);
    }

    const int qr = lane >> 2, qc = lane & 3;
    if (mode == 0) {
        #pragma unroll
        for (int tm = 0; tm < 4; tm++)
            #pragma unroll
            for (int tn = 0; tn < 4; tn++) {
                const int r = m0 + warp_m + tm * 16 + qr;
                const int cN = n0 + warp_n + tn * 8 + qc * 2;
                *(float2*)(Cf + (size_t)r * DM + cN)       = make_float2(acc[tm][tn][0], acc[tm][tn][1]);
                *(float2*)(Cf + (size_t)(r + 8) * DM + cN) = make_float2(acc[tm][tn][2], acc[tm][tn][3]);
            }
    } else if (mode == 1) {
        #pragma unroll
        for (int tm = 0; tm < 4; tm++)
            #pragma unroll
            for (int tn = 0; tn < 4; tn++) {
                const int r = m0 + warp_m + tm * 16 + qr;
                const int pidx = ((n0 + warp_n) >> 1) + tn * 4 + qc;
                unsigned hh, ll;
                split2(make_float2(acc[tm][tn][0] * cscale, acc[tm][tn][1] * cscale), hh, ll);
                Ch[(size_t)r * KP + pidx] = hh; Cl[(size_t)r * KP + pidx] = ll;
                split2(make_float2(acc[tm][tn][2] * cscale, acc[tm][tn][3] * cscale), hh, ll);
                Ch[(size_t)(r + 8) * KP + pidx] = hh; Cl[(size_t)(r + 8) * KP + pidx] = ll;
            }
    } else {
        // stage tile in smem (ring buffers are idle after wait 0), then emit flash layout
        asm volatile("cp.async.wait_group 0;" ::: "memory");
        __syncthreads();
        float* Cst = (float*)sm;    // [128][132] fp32 staging = 67.6 KB <= 96 KB
        #pragma unroll
        for (int tm = 0; tm < 4; tm++)
            #pragma unroll
            for (int tn = 0; tn < 4; tn++) {
                const int r = warp_m + tm * 16 + qr;
                const int c = warp_n + tn * 8 + qc * 2;
                *(float2*)&Cst[r * 132 + c]       = make_float2(acc[tm][tn][0], acc[tm][tn][1]);
                *(float2*)&Cst[(r + 8) * 132 + c] = make_float2(acc[tm][tn][2], acc[tm][tn][3]);
            }
        __syncthreads();
        if (mode == 2) {
            // K: g_Kp[(bh*1024 + j)*32 + kp] = pair(rows 2kp, 2kp+1 @ col j)
            for (int idx = tid; idx < 8192; idx += 256) {
                const int a = idx & 63, j = idx >> 6;
                const int rr = a * 2;
                unsigned hh, ll;
                split2(make_float2(Cst[rr * 132 + j], Cst[(rr + 1) * 132 + j]), hh, ll);
                const size_t o = ((size_t)((m0 + rr) >> 6) * 1024 + n0 + j) * 32 + (a & 31);
                g_Kph[o] = hh; g_Kpl[o] = ll;
            }
        } else {
            // V: g_Vp[(bh*64 + dd)*512 + jp] = pair(cols dd, dd+64 @ row rr)
            for (int idx = tid; idx < 8192; idx += 256) {
                const int dd = idx & 63, rr = idx >> 6;
                unsigned hh, ll;
                split2(make_float2(Cst[rr * 132 + dd], Cst[rr * 132 + dd + 64]), hh, ll);
                const size_t o = ((size_t)((m0 + rr) >> 6) * 64 + dd) * 512
                               + (rr & 63) * 8 + (n0 >> 7);
                g_Vph[o] = hh; g_Vpl[o] = ll;
            }
        }
    }
}

__global__ __launch_bounds__(256, 2) void gemm_qkv()
{
    extern __shared__ char raw[];
    const int z = blockIdx.z;
    const unsigned* Agh = g_inh + (unsigned)z * OFFIN;
    const unsigned* Agl = g_inl + (unsigned)z * OFFIN;
    const unsigned* Bgh = g_wh + (unsigned)z * WOFF;
    const unsigned* Bgl = g_wl + (unsigned)z * WOFF;
    const int mode = (z == 0) ? 1 : (z == 1) ? 2 : 3;
    gemm_body(Agh, Agl, Bgh, Bgl, nullptr, g_Qh, g_Ql, 0.125f, mode,
              (GSmem*)raw, blockIdx.y << 7, blockIdx.x << 7);
}

__global__ __launch_bounds__(256, 2) void gemm_merge(float* __restrict__ out)
{
    extern __shared__ char raw[];
    gemm_body(g_Oh, g_Ol, g_wh + 3u * WOFF, g_wl + 3u * WOFF, out, nullptr, nullptr, 1.f, 0,
              (GSmem*)raw, blockIdx.y << 7, blockIdx.x << 7);
}

// ==================== fused flash attention with relative bias (512 threads) ====================
struct FSmem {
    unsigned Qh[129][36], Ql[129][36];   // Q rows i0..i0+128, pre-scaled 1/8
    unsigned Kh[128][36], Kl[128][36];   // K^T tile (prepacked)
    unsigned Eh[128][36];                // Er window (hi-only)
    unsigned Vh[64][68],  Vl[64][68];    // V tile (prepacked)
    union {
        float G[128][132];
        struct { unsigned Ph[128][68], Pl[128][68]; } pp;
    } u;
    float redmax[128][2];
    float redsum[128][2];
};

__global__ __launch_bounds__(512, 1) void flash_kernel()
{
    extern __shared__ char raw[];
    FSmem* sm = (FSmem*)raw;
    const int tid = threadIdx.x, lane = tid & 31, w = tid >> 5;
    const int qr = lane >> 2, qc = lane & 3;
    const int rg = w & 7, cg = w >> 3;
    const int rg16 = rg << 4;
    const int bh = blockIdx.y, b = bh >> 4, h = bh & 15;
    const int i0 = blockIdx.x << 7;

    #pragma unroll
    for (int it = 0; it < 2; it++) {
        const int idx = tid + it * 512;
        if (idx < 129 * 4) {
            const int r = idx >> 2, ch = idx & 3;
            const int i = i0 + r;
            if (i < SEQ) {
                const size_t base = (size_t)(b * SEQ + h * HD + (i >> 4)) * KP + ((i & 15) << 5) + ch * 8;
                *(uint4*)&sm->Qh[r][ch * 8]     = *(const uint4*)(g_Qh + base);
                *(uint4*)&sm->Qh[r][ch * 8 + 4] = *(const uint4*)(g_Qh + base + 4);
                *(uint4*)&sm->Ql[r][ch * 8]     = *(const uint4*)(g_Ql + base);
                *(uint4*)&sm->Ql[r][ch * 8 + 4] = *(const uint4*)(g_Ql + base + 4);
            } else {
                const uint4 z = make_uint4(0, 0, 0, 0);
                *(uint4*)&sm->Qh[r][ch * 8] = z; *(uint4*)&sm->Qh[r][ch * 8 + 4] = z;
                *(uint4*)&sm->Ql[r][ch * 8] = z; *(uint4*)&sm->Ql[r][ch * 8 + 4] = z;
            }
        }
    }

    float accO[4][4] = {};
    float m0 = -1e30f, m1 = -1e30f, l0 = 0.f, l1 = 0.f;
    const unsigned* kbh = g_Kph + (size_t)bh * 1024 * 32;
    const unsigned* kbl = g_Kpl + (size_t)bh * 1024 * 32;
    const unsigned* vbh = g_Vph + (size_t)bh * 64 * 512;
    const unsigned* vbl = g_Vpl + (size_t)bh * 64 * 512;

    for (int jt = 0; jt < 8; jt++) {
        const int j0 = jt << 7;
        const int delta = j0 - i0;
        float accS[8][4] = {};

        __syncthreads();
        #pragma unroll
        for (int it = 0; it < 2; it++) {
            const int idx = tid + it * 512;
            const int r = idx >> 3, o = (idx & 7) * 4;
            cpa16(sptr(&sm->Kh[r][o]), kbh + (size_t)(j0 + r) * 32 + o);
            cpa16(sptr(&sm->Kl[r][o]), kbl + (size_t)(j0 + r) * 32 + o);
        }
        #pragma unroll
        for (int it = 0; it < 2; it++) {
            const int idx = tid + it * 512;
            const int dd = idx >> 4, o = (idx & 15) * 4;
            cpa16(sptr(&sm->Vh[dd][o]), vbh + (size_t)dd * 512 + (j0 >> 1) + o);
            cpa16(sptr(&sm->Vl[dd][o]), vbl + (size_t)dd * 512 + (j0 >> 1) + o);
        }
        asm volatile("cp.async.commit_group;" ::: "memory");

        #pragma unroll 1
        for (int band = 0; band < 2; band++) {
            if (band == 0 && delta > 0) continue;
            if (band == 1 && delta < 0) continue;
            const int ebase = (band == 0) ? (895 + delta) : (delta - 130);
            #pragma unroll 1
            for (int half = 0; half < 2; half++) {
                if (band == 1 && half == 0 && delta < 128) continue;
                {
                    const int r = tid >> 2, ch = tid & 3;
                    const int er = ebase + half * 128 + r;
                    if (er >= 0 && er < SEQ) {
                        const unsigned* pe = g_Eh + (size_t)er * 32 + ch * 8;
                        *(uint4*)&sm->Eh[r][ch * 8]     = *(const uint4*)pe;
                        *(uint4*)&sm->Eh[r][ch * 8 + 4] = *(const uint4*)(pe + 4);
                    } else {
                        const uint4 z = make_uint4(0, 0, 0, 0);
                        *(uint4*)&sm->Eh[r][ch * 8] = z; *(uint4*)&sm->Eh[r][ch * 8 + 4] = z;
                    }
                }
                __syncthreads();
                const int arow = rg16 + band;
                #pragma unroll 1
                for (int nh = 0; nh < 2; nh++) {
                    float gacc[4][4] = {};
                    const unsigned (*Ehp)[36] = (const unsigned (*)[36])&sm->Eh[cg * 64 + nh * 32];
                    #pragma unroll
                    for (int pb = 0; pb < 32; pb += 8)
                        mma_k16_1<4, 36, 36>(gacc, sm->Qh, Ehp, arow, pb, lane);
                    #pragma unroll
                    for (int tn = 0; tn < 4; tn++) {
                        const int r = rg16 + qr, c = cg * 64 + nh * 32 + tn * 8 + qc * 2;
                        *(float2*)&sm->u.G[r][c]     = make_float2(gacc[tn][0], gacc[tn][1]);
                        *(float2*)&sm->u.G[r + 8][c] = make_float2(gacc[tn][2], gacc[tn][3]);
                    }
                }
                __syncthreads();
                const int lo = (band == 0) ? 0 : max(130 - delta - 128 * half, 0);
                const int hi = (band == 0) ? min(128 - delta - 128 * half, 127) : 127;
                const int span = hi - lo;
                const int base0 = cg * 64 + qc * 2 - (rg16 + qr) + 128 - 128 * half;
                #pragma unroll
                for (int tn = 0; tn < 8; tn++)
                    #pragma unroll
                    for (int k = 0; k < 4; k++) {
                        const int mm = base0 - ((k >> 1) << 3) + tn * 8 + (k & 1);
                        if ((unsigned)(mm - lo) <= (unsigned)span)
                            accS[tn][k] += sm->u.G[rg16 + qr + ((k >> 1) << 3)][mm];
                    }
            }
        }

        asm volatile("cp.async.wait_group 0;" ::: "memory");
        __syncthreads();

        {
            const unsigned (*Khp)[36] = (const unsigned (*)[36])&sm->Kh[cg * 64];
            const unsigned (*Klp)[36] = (const unsigned (*)[36])&sm->Kl[cg * 64];
            #pragma unroll
            for (int pb = 0; pb < 32; pb += 8)
                mma_k16_3<8, 36, 36>(accS, sm->Qh, sm->Ql, Khp, Klp, rg16, pb, lane);
        }

        float tm0 = -1e30f, tm1 = -1e30f;
        #pragma unroll
        for (int tn = 0; tn < 8; tn++) {
            tm0 = fmaxf(tm0, fmaxf(accS[tn][0], accS[tn][1]));
            tm1 = fmaxf(tm1, fmaxf(accS[tn][2], accS[tn][3]));
        }
        tm0 = fmaxf(tm0, __shfl_xor_sync(0xffffffffu, tm0, 1));
        tm0 = fmaxf(tm0, __shfl_xor_sync(0xffffffffu, tm0, 2));
        tm1 = fmaxf(tm1, __shfl_xor_sync(0xffffffffu, tm1, 1));
        tm1 = fmaxf(tm1, __shfl_xor_sync(0xffffffffu, tm1, 2));
        if (qc == 0) {
            sm->redmax[rg16 + qr][cg]     = tm0;
            sm->redmax[rg16 + qr + 8][cg] = tm1;
        }
        __syncthreads();
        const float cm0 = fmaxf(sm->redmax[rg16 + qr][0],     sm->redmax[rg16 + qr][1]);
        const float cm1 = fmaxf(sm->redmax[rg16 + qr + 8][0], sm->redmax[rg16 + qr + 8][1]);
        const float nm0 = fmaxf(m0, cm0), nm1 = fmaxf(m1, cm1);
        const float f0 = __expf(m0 - nm0), f1 = __expf(m1 - nm1);
        float s0 = 0.f, s1 = 0.f;
        #pragma unroll
        for (int tn = 0; tn < 8; tn++) {
            accS[tn][0] = __expf(accS[tn][0] - nm0); s0 += accS[tn][0];
            accS[tn][1] = __expf(accS[tn][1] - nm0); s0 += accS[tn][1];
            accS[tn][2] = __expf(accS[tn][2] - nm1); s1 += accS[tn][2];
            accS[tn][3] = __expf(accS[tn][3] - nm1); s1 += accS[tn][3];
        }
        s0 += __shfl_xor_sync(0xffffffffu, s0, 1); s0 += __shfl_xor_sync(0xffffffffu, s0, 2);
        s1 += __shfl_xor_sync(0xffffffffu, s1, 1); s1 += __shfl_xor_sync(0xffffffffu, s1, 2);
        if (qc == 0) {
            sm->redsum[rg16 + qr][cg]     = s0;
            sm->redsum[rg16 + qr + 8][cg] = s1;
        }

        #pragma unroll
        for (int tn = 0; tn < 8; tn++) {
            unsigned hh, ll;
            split2(make_float2(accS[tn][0], accS[tn][1]), hh, ll);
            sm->u.pp.Ph[rg16 + qr][cg * 32 + tn * 4 + qc] = hh;
            sm->u.pp.Pl[rg16 + qr][cg * 32 + tn * 4 + qc] = ll;
            split2(make_float2(accS[tn][2], accS[tn][3]), hh, ll);
            sm->u.pp.Ph[rg16 + qr + 8][cg * 32 + tn * 4 + qc] = hh;
            sm->u.pp.Pl[rg16 + qr + 8][cg * 32 + tn * 4 + qc] = ll;
        }
        __syncthreads();

        const float cs0 = sm->redsum[rg16 + qr][0]     + sm->redsum[rg16 + qr][1];
        const float cs1 = sm->redsum[rg16 + qr + 8][0] + sm->redsum[rg16 + qr + 8][1];
        l0 = l0 * f0 + cs0; l1 = l1 * f1 + cs1; m0 = nm0; m1 = nm1;
        #pragma unroll
        for (int tn2 = 0; tn2 < 4; tn2++) {
            accO[tn2][0] *= f0; accO[tn2][1] *= f0;
            accO[tn2][2] *= f1; accO[tn2][3] *= f1;
        }

        {
            const unsigned (*Vhp)[68] = (const unsigned (*)[68])&sm->Vh[cg * 32];
            const unsigned (*Vlp)[68] = (const unsigned (*)[68])&sm->Vl[cg * 32];
            #pragma unroll
            for (int pb = 0; pb < 64; pb += 8)
                mma_k16_3<4, 68, 68>(accO, sm->u.pp.Ph, sm->u.pp.Pl, Vhp, Vlp, rg16, pb, lane);
        }
    }

    const float inv0 = 1.f / l0, inv1 = 1.f / l1;
    #pragma unroll
    for (int tn2 = 0; tn2 < 4; tn2++) {
        const int r = i0 + rg16 + qr;
        const int pidx = h * 32 + cg * 16 + tn2 * 4 + qc;
        unsigned hh, ll;
        split2(make_float2(accO[tn2][0] * inv0, accO[tn2][1] * inv0), hh, ll);
        g_Oh[(size_t)(b * SEQ + r) * KP + pidx] = hh;
        g_Ol[(size_t)(b * SEQ + r) * KP + pidx] = ll;
        split2(make_float2(accO[tn2][2] * inv1, accO[tn2][3] * inv1), hh, ll);
        g_Oh[(size_t)(b * SEQ + r + 8) * KP + pidx] = hh;
        g_Ol[(size_t)(b * SEQ + r + 8) * KP + pidx] = ll;
    }
}

// ---------------- launch ----------------
extern "C" void kernel_launch(void* const* d_in, const int* in_sizes, int n_in,
                              void* d_out, int out_size)
{
    const float* query = (const float*)d_in[0];
    const float* key   = (const float*)d_in[1];
    const float* value = (const float*)d_in[2];
    const float* WQ    = (const float*)d_in[3];
    const float* WK    = (const float*)d_in[4];
    const float* WV    = (const float*)d_in[5];
    const float* Er    = (const float*)d_in[6];
    const float* WM    = (const float*)d_in[7];
    float* out = (float*)d_out;

    static bool init = false;
    if (!init) {
        init = true;
        cudaFuncSetAttribute(flash_kernel, cudaFuncAttributeMaxDynamicSharedMemorySize,
                             (int)sizeof(FSmem));
        cudaFuncSetAttribute(gemm_qkv, cudaFuncAttributeMaxDynamicSharedMemorySize,
                             (int)sizeof(GSmem));
        cudaFuncSetAttribute(gemm_merge, cudaFuncAttributeMaxDynamicSharedMemorySize,
                             (int)sizeof(GSmem));
    }

    const int IN8 = MTOK * DM / 8;

    pack_rm3<<<dim3(IN8 / 256, 3), 256>>>(query, key, value);
    pack_er<<<(SEQ * HD / 8) / 256, 256>>>(Er, SEQ * HD / 8);
    pack_cm4<<<dim3(16, 16, 4), 256>>>(WQ, WK, WV, WM);

    gemm_qkv<<<dim3(DM / 128, MTOK / 128, 3), 256, sizeof(GSmem)>>>();
    flash_kernel<<<dim3(SEQ / 128, BH), dim3(512), sizeof(FSmem)>>>();
    gemm_merge<<<dim3(DM / 128, MTOK / 128), 256, sizeof(GSmem)>>>(out);
}

// round 17
// speedup vs baseline: 1.0142x; 1.0142x over previous
#include <cuda_runtime.h>
#include <cuda_bf16.h>

#define BATCH 4
#define SEQ   1024
#define DM    1024
#define HEADS 16
#define HD    64
#define BH    (BATCH*HEADS)
#define MTOK  (BATCH*SEQ)          // 4096
#define KP    (DM/2)               // 512 packed pairs per row
#define OFFIN ((unsigned)MTOK*KP)
#define WOFF  ((unsigned)DM*KP)

// ---------------- scratch (device globals; no allocs allowed) ----------------
__device__ unsigned g_inh[3u*MTOK*KP], g_inl[3u*MTOK*KP];   // packed inputs (q,k,v)
__device__ unsigned g_wh[4u*DM*KP],   g_wl[4u*DM*KP];       // packed weights (col-major)
__device__ unsigned g_Qh[MTOK*KP],    g_Ql[MTOK*KP];        // packed Q projection (pre-scaled by 1/8)
__device__ float    g_K[MTOK*DM],     g_V[MTOK*DM];         // fp32 K,V projections
__device__ unsigned g_Kph[(size_t)BH*SEQ*32], g_Kpl[(size_t)BH*SEQ*32];  // K^T packed
__device__ unsigned g_Vph[(size_t)BH*HD*512], g_Vpl[(size_t)BH*HD*512];  // V packed
__device__ unsigned g_Oh[MTOK*KP],    g_Ol[MTOK*KP];        // packed attention out
__device__ unsigned g_Eh[SEQ*(HD/2)];                       // packed Er (hi only)

// ---------------- helpers ----------------
__device__ __forceinline__ void split2(float2 v, unsigned &h, unsigned &l) {
    __nv_bfloat162 bh = __float22bfloat162_rn(v);
    float2 back = __bfloat1622float2(bh);
    __nv_bfloat162 bl = __float22bfloat162_rn(make_float2(v.x - back.x, v.y - back.y));
    h = *(unsigned*)&bh;
    l = *(unsigned*)&bl;
}

__device__ __forceinline__ unsigned sptr(const void* p) {
    return (unsigned)__cvta_generic_to_shared(p);
}

__device__ __forceinline__ void cpa16(unsigned dst, const void* src) {
    asm volatile("cp.async.cg.shared.global [%0], [%1], 16;" :: "r"(dst), "l"(src) : "memory");
}

__device__ __forceinline__ void ldsm4(unsigned r[4], unsigned a) {
    asm volatile("ldmatrix.sync.aligned.m8n8.x4.shared.b16 {%0,%1,%2,%3}, [%4];"
        : "=r"(r[0]), "=r"(r[1]), "=r"(r[2]), "=r"(r[3]) : "r"(a));
}

__device__ __forceinline__ void mma_bf16(float c[4], const unsigned a[4], const unsigned b[2]) {
    asm volatile(
        "mma.sync.aligned.m16n8k16.row.col.f32.bf16.bf16.f32 "
        "{%0,%1,%2,%3},{%4,%5,%6,%7},{%8,%9},{%0,%1,%2,%3};\n"
        : "+f"(c[0]), "+f"(c[1]), "+f"(c[2]), "+f"(c[3])
        : "r"(a[0]), "r"(a[1]), "r"(a[2]), "r"(a[3]), "r"(b[0]), "r"(b[1]));
}

// pair barrier: warps rg and rg+8 (64 threads) only
#define PAIR_BAR(rg) asm volatile("bar.sync %0, 64;" :: "r"((rg) + 1) : "memory")

// one k16 slab (pair base pb), TN n8-tiles (TN even), 3-term split MMA, ldmatrix feeds.
template<int TN, int PA, int PB>
__device__ __forceinline__ void mma_k16_3(float (*acc)[4],
    const unsigned (*Ah)[PA], const unsigned (*Al)[PA],
    const unsigned (*Bh)[PB], const unsigned (*Bl)[PB],
    int arow, int pb, int lane)
{
    const int ar = arow + (lane & 15);
    const int ac = pb + ((lane >> 4) << 2);
    unsigned ah[4], al[4];
    ldsm4(ah, sptr(&Ah[ar][ac]));
    ldsm4(al, sptr(&Al[ar][ac]));
    const int br = (lane & 7) + ((lane & 16) >> 1);
    const int bc = pb + ((lane & 8) >> 1);
    #pragma unroll
    for (int t2 = 0; t2 < TN / 2; t2++) {
        unsigned bh[4], bl[4];
        ldsm4(bh, sptr(&Bh[t2 * 16 + br][bc]));
        ldsm4(bl, sptr(&Bl[t2 * 16 + br][bc]));
        mma_bf16(acc[2 * t2],     ah, &bh[0]);
        mma_bf16(acc[2 * t2],     al, &bh[0]);
        mma_bf16(acc[2 * t2],     ah, &bl[0]);
        mma_bf16(acc[2 * t2 + 1], ah, &bh[2]);
        mma_bf16(acc[2 * t2 + 1], al, &bh[2]);
        mma_bf16(acc[2 * t2 + 1], ah, &bl[2]);
    }
}

template<int TN, int PA, int PB>
__device__ __forceinline__ void mma_k16_1(float (*acc)[4],
    const unsigned (*Ah)[PA], const unsigned (*Bh)[PB],
    int arow, int pb, int lane)
{
    const int ar = arow + (lane & 15);
    const int ac = pb + ((lane >> 4) << 2);
    unsigned ah[4];
    ldsm4(ah, sptr(&Ah[ar][ac]));
    const int br = (lane & 7) + ((lane & 16) >> 1);
    const int bc = pb + ((lane & 8) >> 1);
    #pragma unroll
    for (int t2 = 0; t2 < TN / 2; t2++) {
        unsigned bh[4];
        ldsm4(bh, sptr(&Bh[t2 * 16 + br][bc]));
        mma_bf16(acc[2 * t2],     ah, &bh[0]);
        mma_bf16(acc[2 * t2 + 1], ah, &bh[2]);
    }
}

// ==================== pack kernels ====================
__global__ __launch_bounds__(256) void pack_rm3(const float* __restrict__ s0,
                                                const float* __restrict__ s1,
                                                const float* __restrict__ s2)
{
    const int z = blockIdx.y;
    const float* src = (z == 0) ? s0 : (z == 1) ? s1 : s2;
    unsigned* dh = g_inh + (unsigned)z * OFFIN;
    unsigned* dl = g_inl + (unsigned)z * OFFIN;
    const int i = blockIdx.x * 256 + threadIdx.x;
    const float4 a = ((const float4*)src)[2 * i], b = ((const float4*)src)[2 * i + 1];
    unsigned h0, l0, h1, l1, h2, l2, h3, l3;
    split2(make_float2(a.x, a.y), h0, l0);
    split2(make_float2(a.z, a.w), h1, l1);
    split2(make_float2(b.x, b.y), h2, l2);
    split2(make_float2(b.z, b.w), h3, l3);
    ((uint4*)dh)[i] = make_uint4(h0, h1, h2, h3);
    ((uint4*)dl)[i] = make_uint4(l0, l1, l2, l3);
}

__global__ __launch_bounds__(256) void pack_er(const float* __restrict__ Er, int n8)
{
    const int i = blockIdx.x * 256 + threadIdx.x;
    if (i < n8) {
        const float4 a = ((const float4*)Er)[2 * i], b = ((const float4*)Er)[2 * i + 1];
        unsigned h0, l0, h1, l1, h2, l2, h3, l3;
        split2(make_float2(a.x, a.y), h0, l0);
        split2(make_float2(a.z, a.w), h1, l1);
        split2(make_float2(b.x, b.y), h2, l2);
        split2(make_float2(b.z, b.w), h3, l3);
        ((uint4*)g_Eh)[i] = make_uint4(h0, h1, h2, h3);
    }
}

__global__ __launch_bounds__(256) void pack_cm4(const float* __restrict__ W0,
                                                const float* __restrict__ W1,
                                                const float* __restrict__ W2,
                                                const float* __restrict__ W3)
{
    __shared__ float s[64][68];
    const int z = blockIdx.z;
    const float* W = (z == 0) ? W0 : (z == 1) ? W1 : (z == 2) ? W2 : W3;
    unsigned* dh = g_wh + (unsigned)z * WOFF;
    unsigned* dl = g_wl + (unsigned)z * WOFF;
    const int tid = threadIdx.x;
    const int k0 = blockIdx.y * 64, c0 = blockIdx.x * 64;
    #pragma unroll
    for (int it = 0; it < 4; it++) {
        const int idx = tid + it * 256;
        const int kr = idx >> 4, cc = (idx & 15) * 4;
        *(float4*)&s[kr][cc] = *(const float4*)(W + (size_t)(k0 + kr) * DM + c0 + cc);
    }
    __syncthreads();
    const int c = tid >> 2, ch = tid & 3;
    unsigned h[8], l[8];
    #pragma unroll
    for (int p = 0; p < 8; p++) {
        const int kp = ch * 8 + p;
        split2(make_float2(s[2 * kp][c], s[2 * kp + 1][c]), h[p], l[p]);
    }
    unsigned* oh = dh + (size_t)(c0 + c) * KP + (k0 >> 1) + ch * 8;
    unsigned* ol = dl + (size_t)(c0 + c) * KP + (k0 >> 1) + ch * 8;
    *(uint4*)oh       = make_uint4(h[0], h[1], h[2], h[3]);
    *(uint4*)(oh + 4) = make_uint4(h[4], h[5], h[6], h[7]);
    *(uint4*)ol       = make_uint4(l[0], l[1], l[2], l[3]);
    *(uint4*)(ol + 4) = make_uint4(l[4], l[5], l[6], l[7]);
}

// ==================== repack K/V (round-13 proven) ====================
__global__ __launch_bounds__(256) void repack_k()
{
    __shared__ float s[64][132];
    const int bh = blockIdx.y, j0 = blockIdx.x * 128;
    const size_t rbase = (size_t)((bh >> 4) * 1024 + (bh & 15) * 64);
    const int tid = threadIdx.x;
    {
        const int r = tid >> 2, q = tid & 3;
        #pragma unroll
        for (int i = 0; i < 8; i++) {
            const int c = q * 32 + i * 4;
            *(float4*)&s[r][c] = *(const float4*)(g_K + (rbase + r) * DM + j0 + c);
        }
    }
    __syncthreads();
    const int lane = tid & 31, w = tid >> 5;
    for (int jj = w; jj < 128; jj += 8) {
        unsigned h, l;
        split2(make_float2(s[2 * lane][jj], s[2 * lane + 1][jj]), h, l);
        const size_t o = ((size_t)bh * 1024 + j0 + jj) * 32 + lane;
        g_Kph[o] = h; g_Kpl[o] = l;
    }
}

__global__ __launch_bounds__(256) void repack_v()
{
    __shared__ float s[8][1024];
    const int bh = blockIdx.y, rg = blockIdx.x;
    const size_t rbase = (size_t)((bh >> 4) * 1024 + (bh & 15) * 64) + rg * 8;
    const int tid = threadIdx.x;
    {
        const int r = tid >> 5, q = tid & 31;
        #pragma unroll
        for (int i = 0; i < 8; i++) {
            const int c = q * 4 + i * 128;
            *(float4*)&s[r][c] = *(const float4*)(g_V + (rbase + r) * DM + c);
        }
    }
    __syncthreads();
    const int lane = tid & 31, w = tid >> 5;
    const int jpl = lane & 7, ddl = lane >> 3;
    for (int it = w; it < 128; it += 8) {
        const int rr = it >> 4, ddg = it & 15;
        const int dd = ddg * 4 + ddl;
        unsigned h, l;
        split2(make_float2(s[rr][2 * jpl * 64 + dd], s[rr][(2 * jpl + 1) * 64 + dd]), h, l);
        const int R = rg * 8 + rr;
        const size_t o = ((size_t)bh * 64 + dd) * 512 + R * 8 + jpl;
        g_Vph[o] = h; g_Vpl[o] = l;
    }
}

// ==================== packed GEMM: 4-stage cp.async ring, BK=16 ====================
struct GSmem { unsigned A[4][2][128][12]; unsigned B[4][2][128][12]; };   // 96 KB

__device__ __forceinline__ void mma16p(const unsigned (*Ah)[12], const unsigned (*Al)[12],
                                       const unsigned (*Bh)[12], const unsigned (*Bl)[12],
                                       float (*acc)[4][4], int warp_m, int warp_n, int lane) {
    const int arl = lane & 15, acl = (lane >> 4) << 2;
    const int brl = (lane & 7) + ((lane & 16) >> 1), bcl = (lane & 8) >> 1;
    unsigned ah[4][4], al[4][4], bh[2][4], bl[2][4];
    #pragma unroll
    for (int tm = 0; tm < 4; tm++) {
        ldsm4(ah[tm], sptr(&Ah[warp_m + tm * 16 + arl][acl]));
        ldsm4(al[tm], sptr(&Al[warp_m + tm * 16 + arl][acl]));
    }
    #pragma unroll
    for (int t2 = 0; t2 < 2; t2++) {
        ldsm4(bh[t2], sptr(&Bh[warp_n + t2 * 16 + brl][bcl]));
        ldsm4(bl[t2], sptr(&Bl[warp_n + t2 * 16 + brl][bcl]));
    }
    #pragma unroll
    for (int tm = 0; tm < 4; tm++)
        #pragma unroll
        for (int t2 = 0; t2 < 2; t2++) {
            mma_bf16(acc[tm][2 * t2],     ah[tm], &bh[t2][0]);
            mma_bf16(acc[tm][2 * t2],     al[tm], &bh[t2][0]);
            mma_bf16(acc[tm][2 * t2],     ah[tm], &bl[t2][0]);
            mma_bf16(acc[tm][2 * t2 + 1], ah[tm], &bh[t2][2]);
            mma_bf16(acc[tm][2 * t2 + 1], al[tm], &bh[t2][2]);
            mma_bf16(acc[tm][2 * t2 + 1], ah[tm], &bl[t2][2]);
        }
}

__device__ __forceinline__ void gemm_body(
    const unsigned* Agh, const unsigned* Agl,
    const unsigned* Bgh, const unsigned* Bgl,
    float* Cf, unsigned* Ch, unsigned* Cl, float cscale,
    GSmem* sm, int m0, int n0)
{
    const int tid = threadIdx.x, lane = tid & 31, w = tid >> 5;
    const int warp_m = (w >> 2) * 64, warp_n = (w & 3) * 32;
    const int lrow = tid >> 1, loff = (tid & 1) << 2;
    const unsigned* Ash = Agh + (size_t)(m0 + lrow) * KP + loff;
    const unsigned* Asl = Agl + (size_t)(m0 + lrow) * KP + loff;
    const unsigned* Bsh = Bgh + (size_t)(n0 + lrow) * KP + loff;
    const unsigned* Bsl = Bgl + (size_t)(n0 + lrow) * KP + loff;

    auto load = [&](int s, int st) {
        const int kp0 = s << 3;
        cpa16(sptr(&sm->A[st][0][lrow][loff]), Ash + kp0);
        cpa16(sptr(&sm->A[st][1][lrow][loff]), Asl + kp0);
        cpa16(sptr(&sm->B[st][0][lrow][loff]), Bsh + kp0);
        cpa16(sptr(&sm->B[st][1][lrow][loff]), Bsl + kp0);
        asm volatile("cp.async.commit_group;" ::: "memory");
    };

    float acc[4][4][4] = {};
    load(0, 0); load(1, 1); load(2, 2);
    for (int s = 0; s < 64; s++) {
        const int st = s & 3;
        asm volatile("cp.async.wait_group 2;" ::: "memory");
        __syncthreads();
        if (s < 61) load(s + 3, (s + 3) & 3);
        else        asm volatile("cp.async.commit_group;" ::: "memory");
        mma16p(sm->A[st][0], sm->A[st][1], sm->B[st][0], sm->B[st][1],
               acc, warp_m, warp_n, lane);
    }

    const int qr = lane >> 2, qc = lane & 3;
    if (Cf) {
        #pragma unroll
        for (int tm = 0; tm < 4; tm++)
            #pragma unroll
            for (int tn = 0; tn < 4; tn++) {
                const int r = m0 + warp_m + tm * 16 + qr;
                const int cN = n0 + warp_n + tn * 8 + qc * 2;
                *(float2*)(Cf + (size_t)r * DM + cN)       = make_float2(acc[tm][tn][0], acc[tm][tn][1]);
                *(float2*)(Cf + (size_t)(r + 8) * DM + cN) = make_float2(acc[tm][tn][2], acc[tm][tn][3]);
            }
    } else {
        #pragma unroll
        for (int tm = 0; tm < 4; tm++)
            #pragma unroll
            for (int tn = 0; tn < 4; tn++) {
                const int r = m0 + warp_m + tm * 16 + qr;
                const int pidx = ((n0 + warp_n) >> 1) + tn * 4 + qc;
                unsigned hh, ll;
                split2(make_float2(acc[tm][tn][0] * cscale, acc[tm][tn][1] * cscale), hh, ll);
                Ch[(size_t)r * KP + pidx] = hh; Cl[(size_t)r * KP + pidx] = ll;
                split2(make_float2(acc[tm][tn][2] * cscale, acc[tm][tn][3] * cscale), hh, ll);
                Ch[(size_t)(r + 8) * KP + pidx] = hh; Cl[(size_t)(r + 8) * KP + pidx] = ll;
            }
    }
}

__global__ __launch_bounds__(256, 2) void gemm_qkv()
{
    extern __shared__ char raw[];
    const int z = blockIdx.z;
    const unsigned* Agh = g_inh + (unsigned)z * OFFIN;
    const unsigned* Agl = g_inl + (unsigned)z * OFFIN;
    const unsigned* Bgh = g_wh + (unsigned)z * WOFF;
    const unsigned* Bgl = g_wl + (unsigned)z * WOFF;
    float* Cf = (z == 1) ? g_K : (z == 2) ? g_V : nullptr;
    gemm_body(Agh, Agl, Bgh, Bgl, Cf, g_Qh, g_Ql, 0.125f,
              (GSmem*)raw, blockIdx.y << 7, blockIdx.x << 7);
}

__global__ __launch_bounds__(256, 2) void gemm_merge(float* __restrict__ out)
{
    extern __shared__ char raw[];
    gemm_body(g_Oh, g_Ol, g_wh + 3u * WOFF, g_wl + 3u * WOFF, out, nullptr, nullptr, 1.f,
              (GSmem*)raw, blockIdx.y << 7, blockIdx.x << 7);
}

// ==================== fused flash attention (pair barriers) ====================
struct FSmem {
    unsigned Qh[129][36], Ql[129][36];   // Q rows i0..i0+128, pre-scaled 1/8
    unsigned Kh[128][36], Kl[128][36];   // K^T tile (prepacked)
    unsigned Eh[128][36];                // Er window (hi-only)
    unsigned Vh[64][68],  Vl[64][68];    // V tile (prepacked)
    union {
        float G[128][132];
        struct { unsigned Ph[128][68], Pl[128][68]; } pp;
    } u;
    float redmax[128][2];
    float redsum[128][2];
};

__global__ __launch_bounds__(512, 1) void flash_kernel()
{
    extern __shared__ char raw[];
    FSmem* sm = (FSmem*)raw;
    const int tid = threadIdx.x, lane = tid & 31, w = tid >> 5;
    const int qr = lane >> 2, qc = lane & 3;
    const int rg = w & 7, cg = w >> 3;
    const int rg16 = rg << 4;
    const int bh = blockIdx.y, b = bh >> 4, h = bh & 15;
    const int i0 = blockIdx.x << 7;

    #pragma unroll
    for (int it = 0; it < 2; it++) {
        const int idx = tid + it * 512;
        if (idx < 129 * 4) {
            const int r = idx >> 2, ch = idx & 3;
            const int i = i0 + r;
            if (i < SEQ) {
                const size_t base = (size_t)(b * SEQ + h * HD + (i >> 4)) * KP + ((i & 15) << 5) + ch * 8;
                *(uint4*)&sm->Qh[r][ch * 8]     = *(const uint4*)(g_Qh + base);
                *(uint4*)&sm->Qh[r][ch * 8 + 4] = *(const uint4*)(g_Qh + base + 4);
                *(uint4*)&sm->Ql[r][ch * 8]     = *(const uint4*)(g_Ql + base);
                *(uint4*)&sm->Ql[r][ch * 8 + 4] = *(const uint4*)(g_Ql + base + 4);
            } else {
                const uint4 z = make_uint4(0, 0, 0, 0);
                *(uint4*)&sm->Qh[r][ch * 8] = z; *(uint4*)&sm->Qh[r][ch * 8 + 4] = z;
                *(uint4*)&sm->Ql[r][ch * 8] = z; *(uint4*)&sm->Ql[r][ch * 8 + 4] = z;
            }
        }
    }

    float accO[4][4] = {};
    float m0 = -1e30f, m1 = -1e30f, l0 = 0.f, l1 = 0.f;
    const unsigned* kbh = g_Kph + (size_t)bh * 1024 * 32;
    const unsigned* kbl = g_Kpl + (size_t)bh * 1024 * 32;
    const unsigned* vbh = g_Vph + (size_t)bh * 64 * 512;
    const unsigned* vbl = g_Vpl + (size_t)bh * 64 * 512;

    for (int jt = 0; jt < 8; jt++) {
        const int j0 = jt << 7;
        const int delta = j0 - i0;
        float accS[8][4] = {};

        // ---- full sync: prior tile's K/V reads done before overwriting; then prefetch ----
        __syncthreads();
        #pragma unroll
        for (int it = 0; it < 2; it++) {
            const int idx = tid + it * 512;
            const int r = idx >> 3, o = (idx & 7) * 4;
            cpa16(sptr(&sm->Kh[r][o]), kbh + (size_t)(j0 + r) * 32 + o);
            cpa16(sptr(&sm->Kl[r][o]), kbl + (size_t)(j0 + r) * 32 + o);
        }
        #pragma unroll
        for (int it = 0; it < 2; it++) {
            const int idx = tid + it * 512;
            const int dd = idx >> 4, o = (idx & 15) * 4;
            cpa16(sptr(&sm->Vh[dd][o]), vbh + (size_t)dd * 512 + (j0 >> 1) + o);
            cpa16(sptr(&sm->Vl[dd][o]), vbl + (size_t)dd * 512 + (j0 >> 1) + o);
        }
        asm volatile("cp.async.commit_group;" ::: "memory");

        // ---- relative-bias phases ----
        #pragma unroll 1
        for (int band = 0; band < 2; band++) {
            if (band == 0 && delta > 0) continue;
            if (band == 1 && delta < 0) continue;
            const int ebase = (band == 0) ? (895 + delta) : (delta - 130);
            #pragma unroll 1
            for (int half = 0; half < 2; half++) {
                if (band == 1 && half == 0 && delta < 128) continue;
                {
                    const int r = tid >> 2, ch = tid & 3;
                    const int er = ebase + half * 128 + r;
                    if (er >= 0 && er < SEQ) {
                        const unsigned* pe = g_Eh + (size_t)er * 32 + ch * 8;
                        *(uint4*)&sm->Eh[r][ch * 8]     = *(const uint4*)pe;
                        *(uint4*)&sm->Eh[r][ch * 8 + 4] = *(const uint4*)(pe + 4);
                    } else {
                        const uint4 z = make_uint4(0, 0, 0, 0);
                        *(uint4*)&sm->Eh[r][ch * 8] = z; *(uint4*)&sm->Eh[r][ch * 8 + 4] = z;
                    }
                }
                __syncthreads();   // full: E written by all threads, read by all pairs
                const int arow = rg16 + band;
                #pragma unroll 1
                for (int nh = 0; nh < 2; nh++) {
                    float gacc[4][4] = {};
                    const unsigned (*Ehp)[36] = (const unsigned (*)[36])&sm->Eh[cg * 64 + nh * 32];
                    #pragma unroll
                    for (int pb = 0; pb < 32; pb += 8)
                        mma_k16_1<4, 36, 36>(gacc, sm->Qh, Ehp, arow, pb, lane);
                    #pragma unroll
                    for (int tn = 0; tn < 4; tn++) {
                        const int r = rg16 + qr, c = cg * 64 + nh * 32 + tn * 8 + qc * 2;
                        *(float2*)&sm->u.G[r][c]     = make_float2(gacc[tn][0], gacc[tn][1]);
                        *(float2*)&sm->u.G[r + 8][c] = make_float2(gacc[tn][2], gacc[tn][3]);
                    }
                }
                PAIR_BAR(rg);      // G rows rg16.. are pair-local (cols split across cg pair)
                const int lo = (band == 0) ? 0 : max(130 - delta - 128 * half, 0);
                const int hi = (band == 0) ? min(128 - delta - 128 * half, 127) : 127;
                const int span = hi - lo;
                const int base0 = cg * 64 + qc * 2 - (rg16 + qr) + 128 - 128 * half;
                #pragma unroll
                for (int tn = 0; tn < 8; tn++)
                    #pragma unroll
                    for (int k = 0; k < 4; k++) {
                        const int mm = base0 - ((k >> 1) << 3) + tn * 8 + (k & 1);
                        if ((unsigned)(mm - lo) <= (unsigned)span)
                            accS[tn][k] += sm->u.G[rg16 + qr + ((k >> 1) << 3)][mm];
                    }
            }
        }

        // ---- full sync: K/V cp.async complete and visible to all ----
        asm volatile("cp.async.wait_group 0;" ::: "memory");
        __syncthreads();

        {
            const unsigned (*Khp)[36] = (const unsigned (*)[36])&sm->Kh[cg * 64];
            const unsigned (*Klp)[36] = (const unsigned (*)[36])&sm->Kl[cg * 64];
            #pragma unroll
            for (int pb = 0; pb < 32; pb += 8)
                mma_k16_3<8, 36, 36>(accS, sm->Qh, sm->Ql, Khp, Klp, rg16, pb, lane);
        }

        float tm0 = -1e30f, tm1 = -1e30f;
        #pragma unroll
        for (int tn = 0; tn < 8; tn++) {
            tm0 = fmaxf(tm0, fmaxf(accS[tn][0], accS[tn][1]));
            tm1 = fmaxf(tm1, fmaxf(accS[tn][2], accS[tn][3]));
        }
        tm0 = fmaxf(tm0, __shfl_xor_sync(0xffffffffu, tm0, 1));
        tm0 = fmaxf(tm0, __shfl_xor_sync(0xffffffffu, tm0, 2));
        tm1 = fmaxf(tm1, __shfl_xor_sync(0xffffffffu, tm1, 1));
        tm1 = fmaxf(tm1, __shfl_xor_sync(0xffffffffu, tm1, 2));
        if (qc == 0) {
            sm->redmax[rg16 + qr][cg]     = tm0;
            sm->redmax[rg16 + qr + 8][cg] = tm1;
        }
        PAIR_BAR(rg);              // redmax rows are pair-local
        const float cm0 = fmaxf(sm->redmax[rg16 + qr][0],     sm->redmax[rg16 + qr][1]);
        const float cm1 = fmaxf(sm->redmax[rg16 + qr + 8][0], sm->redmax[rg16 + qr + 8][1]);
        const float nm0 = fmaxf(m0, cm0), nm1 = fmaxf(m1, cm1);
        const float f0 = __expf(m0 - nm0), f1 = __expf(m1 - nm1);
        float s0 = 0.f, s1 = 0.f;
        #pragma unroll
        for (int tn = 0; tn < 8; tn++) {
            accS[tn][0] = __expf(accS[tn][0] - nm0); s0 += accS[tn][0];
            accS[tn][1] = __expf(accS[tn][1] - nm0); s0 += accS[tn][1];
            accS[tn][2] = __expf(accS[tn][2] - nm1); s1 += accS[tn][2];
            accS[tn][3] = __expf(accS[tn][3] - nm1); s1 += accS[tn][3];
        }
        s0 += __shfl_xor_sync(0xffffffffu, s0, 1); s0 += __shfl_xor_sync(0xffffffffu, s0, 2);
        s1 += __shfl_xor_sync(0xffffffffu, s1, 1); s1 += __shfl_xor_sync(0xffffffffu, s1, 2);
        if (qc == 0) {
            sm->redsum[rg16 + qr][cg]     = s0;
            sm->redsum[rg16 + qr + 8][cg] = s1;
        }

        #pragma unroll
        for (int tn = 0; tn < 8; tn++) {
            unsigned hh, ll;
            split2(make_float2(accS[tn][0], accS[tn][1]), hh, ll);
            sm->u.pp.Ph[rg16 + qr][cg * 32 + tn * 4 + qc] = hh;
            sm->u.pp.Pl[rg16 + qr][cg * 32 + tn * 4 + qc] = ll;
            split2(make_float2(accS[tn][2], accS[tn][3]), hh, ll);
            sm->u.pp.Ph[rg16 + qr + 8][cg * 32 + tn * 4 + qc] = hh;
            sm->u.pp.Pl[rg16 + qr + 8][cg * 32 + tn * 4 + qc] = ll;
        }
        PAIR_BAR(rg);              // P rows + redsum rows are pair-local

        const float cs0 = sm->redsum[rg16 + qr][0]     + sm->redsum[rg16 + qr][1];
        const float cs1 = sm->redsum[rg16 + qr + 8][0] + sm->redsum[rg16 + qr + 8][1];
        l0 = l0 * f0 + cs0; l1 = l1 * f1 + cs1; m0 = nm0; m1 = nm1;
        #pragma unroll
        for (int tn2 = 0; tn2 < 4; tn2++) {
            accO[tn2][0] *= f0; accO[tn2][1] *= f0;
            accO[tn2][2] *= f1; accO[tn2][3] *= f1;
        }

        {
            const unsigned (*Vhp)[68] = (const unsigned (*)[68])&sm->Vh[cg * 32];
            const unsigned (*Vlp)[68] = (const unsigned (*)[68])&sm->Vl[cg * 32];
            #pragma unroll
            for (int pb = 0; pb < 64; pb += 8)
                mma_k16_3<4, 68, 68>(accO, sm->u.pp.Ph, sm->u.pp.Pl, Vhp, Vlp, rg16, pb, lane);
        }
    }

    const float inv0 = 1.f / l0, inv1 = 1.f / l1;
    #pragma unroll
    for (int tn2 = 0; tn2 < 4; tn2++) {
        const int r = i0 + rg16 + qr;
        const int pidx = h * 32 + cg * 16 + tn2 * 4 + qc;
        unsigned hh, ll;
        split2(make_float2(accO[tn2][0] * inv0, accO[tn2][1] * inv0), hh, ll);
        g_Oh[(size_t)(b * SEQ + r) * KP + pidx] = hh;
        g_Ol[(size_t)(b * SEQ + r) * KP + pidx] = ll;
        split2(make_float2(accO[tn2][2] * inv1, accO[tn2][3] * inv1), hh, ll);
        g_Oh[(size_t)(b * SEQ + r + 8) * KP + pidx] = hh;
        g_Ol[(size_t)(b * SEQ + r + 8) * KP + pidx] = ll;
    }
}

// ---------------- launch ----------------
extern "C" void kernel_launch(void* const* d_in, const int* in_sizes, int n_in,
                              void* d_out, int out_size)
{
    const float* query = (const float*)d_in[0];
    const float* key   = (const float*)d_in[1];
    const float* value = (const float*)d_in[2];
    const float* WQ    = (const float*)d_in[3];
    const float* WK    = (const float*)d_in[4];
    const float* WV    = (const float*)d_in[5];
    const float* Er    = (const float*)d_in[6];
    const float* WM    = (const float*)d_in[7];
    float* out = (float*)d_out;

    static bool init = false;
    if (!init) {
        init = true;
        cudaFuncSetAttribute(flash_kernel, cudaFuncAttributeMaxDynamicSharedMemorySize,
                             (int)sizeof(FSmem));
        cudaFuncSetAttribute(gemm_qkv, cudaFuncAttributeMaxDynamicSharedMemorySize,
                             (int)sizeof(GSmem));
        cudaFuncSetAttribute(gemm_merge, cudaFuncAttributeMaxDynamicSharedMemorySize,
                             (int)sizeof(GSmem));
    }

    const int IN8 = MTOK * DM / 8;

    pack_rm3<<<dim3(IN8 / 256, 3), 256>>>(query, key, value);
    pack_er<<<(SEQ * HD / 8) / 256, 256>>>(Er, SEQ * HD / 8);
    pack_cm4<<<dim3(16, 16, 4), 256>>>(WQ, WK, WV, WM);

    gemm_qkv<<<dim3(DM / 128, MTOK / 128, 3), 256, sizeof(GSmem)>>>();
    repack_k<<<dim3(8, BH), 256>>>();
    repack_v<<<dim3(8, BH), 256>>>();
    flash_kernel<<<dim3(SEQ / 128, BH), dim3(512), sizeof(FSmem)>>>();
    gemm_merge<<<dim3(DM / 128, MTOK / 128), 256, sizeof(GSmem)>>>(out);
}